// round 3
// baseline (speedup 1.0000x reference)
#include <cuda_runtime.h>
#include <math.h>

// Problem constants (fixed by the dataset)
#define P_PRED 3
#define E_EV   128
#define CHUNKS 8
#define TPB    256

#define TIME_TOL 0.1f
#define DECAY    0.8f
#define RES_D    0.03
#define WINDOW   25.0f   // exp(-0.8*25) ~ 2e-9: below f32 sum noise, safe to drop

// Deterministic partial-sum scratch (no device allocation allowed).
__device__ double g_partials[2048];

// Count of entries arr[0..n) with (t - arr[i]) > thr; arr sorted ascending.
// For thr = 0.1f this is the reference indicator, bit-exact (monotone f32 predicate).
__device__ __forceinline__ int cut_count(const float* __restrict__ arr, int n,
                                         float t, float thr) {
    int lo = 0, hi = n;
    while (lo < hi) {
        int mid = (lo + hi) >> 1;
        if ((t - arr[mid]) > thr) lo = mid + 1; else hi = mid;
    }
    return lo;
}

// k_p(t) = sum over included masked events of exp(-0.8*(t - te)),
// summed in ascending-te order (reference order), per-term f32 exp.
__device__ __forceinline__ float kernel_sum(const float* __restrict__ ct, int n, float t) {
    int hi = cut_count(ct, n, t, TIME_TOL);
    int lo = cut_count(ct, n, t, WINDOW);
    float k = 0.0f;
    for (int e = lo; e < hi; ++e) {
        k = __fadd_rn(k, __expf(__fmul_rn(-DECAY, __fsub_rn(t, ct[e]))));
    }
    return k;
}

__device__ __forceinline__ float final_intensity(float raw, float base) {
    return (raw >= 0.0f) ? fmaxf(raw, base) : __expf(raw);
}

__device__ __forceinline__ float lam_of(float w, float feat, float b) {
    float raw = __fadd_rn(b, __fmul_rn(w, feat));   // mirror ref: mul then add, no FMA
    return final_intensity(raw, b);
}

__global__ __launch_bounds__(TPB)
void hawkes_kernel(const float* __restrict__ event_times,
                   const float* __restrict__ event_mask,
                   const float* __restrict__ base,
                   const float* __restrict__ weight,
                   const void*  __restrict__ tmax_ptr) {
    const int s     = blockIdx.x / CHUNKS;
    const int chunk = blockIdx.x % CHUNKS;
    const int tid   = threadIdx.x;

    __shared__ float st[P_PRED][E_EV];   // full event times (for queries)
    __shared__ float sm[P_PRED][E_EV];   // masks
    __shared__ float ct[P_PRED][E_EV];   // compacted active event times (sorted)
    __shared__ int   cn[P_PRED];         // active counts
    __shared__ float sb[P_PRED], sw[P_PRED];

    const float* et = event_times + (size_t)s * P_PRED * E_EV;
    const float* em = event_mask  + (size_t)s * P_PRED * E_EV;
    for (int i = tid; i < P_PRED * E_EV; i += TPB) {
        int p = i >> 7, e = i & 127;
        st[p][e] = et[i];
        sm[p][e] = em[i];
    }
    if (tid < P_PRED) { sb[tid] = base[tid]; sw[tid] = weight[tid]; }
    __syncthreads();

    // Compact active events per predicate (keeps sorted order).
    if (tid < P_PRED) {
        int n = 0;
        for (int e = 0; e < E_EV; ++e)
            if (sm[tid][e] > 0.0f) ct[tid][n++] = st[tid][e];
        cn[tid] = n;
    }
    __syncthreads();

    // Grid count G = ceil(T_max / 0.03); T_max may arrive as int32/int64 or f32.
    int tmax_i = *(const int*)tmax_ptr;
    if (!(tmax_i > 0 && tmax_i < 1000000)) tmax_i = (int)(*(const float*)tmax_ptr);
    const int G = (int)ceil((double)tmax_i / RES_D);

    const float b0 = sb[0], b1 = sb[1], b2 = sb[2];
    const float w0 = sw[0], w1 = sw[1], w2 = sw[2];
    const int n0 = cn[0], n1 = cn[1], n2 = cn[2];

    double acc_int = 0.0;
    double acc_log = 0.0;

    // ---- integral term over this chunk's grid points ----
    const int per = (G + CHUNKS - 1) / CHUNKS;
    const int gs = chunk * per;
    const int ge = min(gs + per, G);
    for (int g = gs + tid; g < ge; g += TPB) {
        float t = (float)((double)g * RES_D);   // matches np.arange(f64) cast to f32
        float k0 = kernel_sum(ct[0], n0, t);
        float k1 = kernel_sum(ct[1], n1, t);
        float k2 = kernel_sum(ct[2], n2, t);
        // BODY = [[0,1,1],[1,0,0],[1,0,0]]
        float l0 = lam_of(w0, __fadd_rn(k1, k2), b0);
        float l1 = lam_of(w1, k0, b1);
        float l2 = lam_of(w2, k0, b2);
        acc_int += (double)l0 + (double)l1 + (double)l2;
    }

    // ---- log-sum term: queries are each head's own event times, eq>=1, mask>0 ----
    const int QTOT = P_PRED * E_EV;            // 384
    const int qper = QTOT / CHUNKS;            // 48
    const int qsrt = chunk * qper;
    for (int q = qsrt + tid; q < qsrt + qper; q += TPB) {
        int h = q >> 7, eq = q & 127;
        if (eq < 1) continue;
        if (!(sm[h][eq] > 0.0f)) continue;
        float tq = st[h][eq];
        float feat;
        if (h == 0) {
            float k1 = kernel_sum(ct[1], n1, tq);
            float k2 = kernel_sum(ct[2], n2, tq);
            feat = __fadd_rn(k1, k2);
        } else {
            feat = kernel_sum(ct[0], n0, tq);
        }
        float bh = (h == 0) ? b0 : (h == 1) ? b1 : b2;
        float wh = (h == 0) ? w0 : (h == 1) ? w1 : w2;
        float lam = lam_of(wh, feat, bh);
        acc_log += (double)logf(lam);
    }

    // ---- deterministic block reduce, store partial ----
    __shared__ double red[TPB];
    red[tid] = acc_log - (double)RES_D * acc_int;
    __syncthreads();
#pragma unroll
    for (int off = TPB / 2; off > 0; off >>= 1) {
        if (tid < off) red[tid] += red[tid + off];
        __syncthreads();
    }
    if (tid == 0) g_partials[blockIdx.x] = red[0];
}

__global__ __launch_bounds__(TPB)
void reduce_kernel(float* __restrict__ out, int nblocks) {
    __shared__ double red[TPB];
    double a = 0.0;
    for (int i = threadIdx.x; i < nblocks; i += TPB) a += g_partials[i];
    red[threadIdx.x] = a;
    __syncthreads();
#pragma unroll
    for (int off = TPB / 2; off > 0; off >>= 1) {
        if (threadIdx.x < off) red[threadIdx.x] += red[threadIdx.x + off];
        __syncthreads();
    }
    if (threadIdx.x == 0) out[0] = (float)red[0];
}

extern "C" void kernel_launch(void* const* d_in, const int* in_sizes, int n_in,
                              void* d_out, int out_size) {
    const float* event_times = (const float*)d_in[0];
    const float* event_mask  = (const float*)d_in[1];
    const float* base        = (const float*)d_in[2];
    const float* weight      = (const float*)d_in[3];
    const void*  tmax        = d_in[4];

    int S = in_sizes[0] / (P_PRED * E_EV);
    int nblocks = S * CHUNKS;

    hawkes_kernel<<<nblocks, TPB>>>(event_times, event_mask, base, weight, tmax);
    reduce_kernel<<<1, TPB>>>((float*)d_out, nblocks);
}

// round 5
// speedup vs baseline: 1.1794x; 1.1794x over previous
#include <cuda_runtime.h>
#include <math.h>
#include <float.h>

// Problem constants (fixed by the dataset)
#define P_PRED 3
#define E_EV   128
#define CHUNKS 16
#define TPB    128

#define TIME_TOL 0.1f
#define DECAY    0.8f
#define RES_D    0.03
#define WINDOW   25.0f   // exp(-0.8*25) ~ 2e-9: vanishes in the f32 sum

// Scratch (no device allocation allowed anywhere).
__device__ double g_partials[2048];
__device__ int    g_counter = 0;

__device__ __forceinline__ float final_intensity(float raw, float base) {
    return (raw >= 0.0f) ? fmaxf(raw, base) : __expf(raw);
}

__device__ __forceinline__ float lam_of(float w, float feat, float b) {
    float raw = __fadd_rn(b, __fmul_rn(w, feat));   // mirror ref: mul then add
    return final_intensity(raw, b);
}

// Faithful kernel-sum for the q-loop: padded array, fixed 8-step search.
// (129 possible insertion points for 128 elements -> 8 iterations required.)
__device__ __forceinline__ float kernel_sum_one(const float* __restrict__ ct, float t) {
    int aT = 0, bT = E_EV, aW = 0, bW = E_EV;
#pragma unroll
    for (int it = 0; it < 8; ++it) {
        int mT = (aT + bT) >> 1;  float vT = ct[mT];
        int mW = (aW + bW) >> 1;  float vW = ct[mW];
        bool pT = (aT < bT) && ((t - vT) > TIME_TOL);
        bool pW = (aW < bW) && ((t - vW) > WINDOW);
        if (aT < bT) { aT = pT ? mT + 1 : aT;  bT = pT ? bT : mT; }
        if (aW < bW) { aW = pW ? mW + 1 : aW;  bW = pW ? bW : mW; }
    }
    float k = 0.0f;
    for (int e = aW; e < aT; ++e)
        k = __fadd_rn(k, __expf(__fmul_rn(-DECAY, __fsub_rn(t, ct[e]))));
    return k;
}

__global__ __launch_bounds__(TPB)
void hawkes_fused(const float* __restrict__ event_times,
                  const float* __restrict__ event_mask,
                  const float* __restrict__ base,
                  const float* __restrict__ weight,
                  const void*  __restrict__ tmax_ptr,
                  float* __restrict__ out) {
    const int s     = blockIdx.x / CHUNKS;
    const int chunk = blockIdx.x % CHUNKS;
    const int tid   = threadIdx.x;
    const int NB    = gridDim.x;

    __shared__ float st[P_PRED][E_EV];   // full event times (queries)
    __shared__ float sm[P_PRED][E_EV];   // masks
    __shared__ float ct[P_PRED][E_EV];   // compacted active times, FLT_MAX padded
    __shared__ float sb[P_PRED], sw[P_PRED];
    __shared__ double red[TPB];
    __shared__ int islast;

    const float* et = event_times + (size_t)s * P_PRED * E_EV;
    const float* em = event_mask  + (size_t)s * P_PRED * E_EV;
    for (int i = tid; i < P_PRED * E_EV; i += TPB) {
        int p = i >> 7, e = i & 127;
        st[p][e] = et[i];
        sm[p][e] = em[i];
    }
    if (tid < P_PRED) { sb[tid] = base[tid]; sw[tid] = weight[tid]; }
    __syncthreads();

    // Order-preserving warp-ballot compaction: warp w handles predicate w.
    const int wid  = tid >> 5, lane = tid & 31;
    if (wid < P_PRED) {
        unsigned lt = (1u << lane) - 1u;
        int nbase = 0;
#pragma unroll
        for (int r = 0; r < E_EV / 32; ++r) {
            int e = r * 32 + lane;
            float mv = sm[wid][e];
            float tv = st[wid][e];
            unsigned bal = __ballot_sync(0xffffffffu, mv > 0.0f);
            if (mv > 0.0f) ct[wid][nbase + __popc(bal & lt)] = tv;
            nbase += __popc(bal);
        }
        for (int e = nbase + lane; e < E_EV; e += 32) ct[wid][e] = FLT_MAX;
    }
    __syncthreads();

    // Grid count G = ceil(T_max / 0.03); T_max may arrive as int or f32.
    int tmax_i = *(const int*)tmax_ptr;
    if (!(tmax_i > 0 && tmax_i < 1000000)) tmax_i = (int)(*(const float*)tmax_ptr);
    const int G = (int)ceil((double)tmax_i / RES_D);

    const float b0 = sb[0], b1 = sb[1], b2 = sb[2];
    const float w0 = sw[0], w1 = sw[1], w2 = sw[2];

    double acc_int = 0.0;
    double acc_log = 0.0;

    // ---- integral term over this chunk's grid points ----
    const int per = (G + CHUNKS - 1) / CHUNKS;
    const int gs = chunk * per;
    const int ge = min(gs + per, G);
    for (int g = gs + tid; g < ge; g += TPB) {
        float t = (float)((double)g * RES_D);   // matches np.arange(f64) -> f32

        // Lockstep 6-way binary search (3 preds x {TIME_TOL, WINDOW}), 8 steps.
        int aT[P_PRED], bT[P_PRED], aW[P_PRED], bW[P_PRED];
#pragma unroll
        for (int p = 0; p < P_PRED; ++p) { aT[p] = aW[p] = 0; bT[p] = bW[p] = E_EV; }
#pragma unroll
        for (int it = 0; it < 8; ++it) {
#pragma unroll
            for (int p = 0; p < P_PRED; ++p) {
                int mT = (aT[p] + bT[p]) >> 1;  float vT = ct[p][mT];
                int mW = (aW[p] + bW[p]) >> 1;  float vW = ct[p][mW];
                bool pT = (aT[p] < bT[p]) && ((t - vT) > TIME_TOL);
                bool pW = (aW[p] < bW[p]) && ((t - vW) > WINDOW);
                if (aT[p] < bT[p]) { aT[p] = pT ? mT + 1 : aT[p];  bT[p] = pT ? bT[p] : mT; }
                if (aW[p] < bW[p]) { aW[p] = pW ? mW + 1 : aW[p];  bW[p] = pW ? bW[p] : mW; }
            }
        }
        int s0 = aW[0], c0 = aT[0] - aW[0];
        int s1 = aW[1], c1 = aT[1] - aW[1];
        int s2 = aW[2], c2 = aT[2] - aW[2];
        int mx = max(c0, max(c1, c2));

        // Fused predicated sum: 3 independent FADD chains, per-pred order preserved.
        float k0 = 0.0f, k1 = 0.0f, k2 = 0.0f;
        for (int j = 0; j < mx; ++j) {
            if (j < c0) k0 = __fadd_rn(k0, __expf(__fmul_rn(-DECAY, __fsub_rn(t, ct[0][s0 + j]))));
            if (j < c1) k1 = __fadd_rn(k1, __expf(__fmul_rn(-DECAY, __fsub_rn(t, ct[1][s1 + j]))));
            if (j < c2) k2 = __fadd_rn(k2, __expf(__fmul_rn(-DECAY, __fsub_rn(t, ct[2][s2 + j]))));
        }

        // BODY = [[0,1,1],[1,0,0],[1,0,0]]
        float l0 = lam_of(w0, __fadd_rn(k1, k2), b0);
        float l1 = lam_of(w1, k0, b1);
        float l2 = lam_of(w2, k0, b2);
        acc_int += (double)l0 + (double)l1 + (double)l2;
    }

    // ---- log-sum term: each head's own event times, eq >= 1, mask > 0 ----
    const int QPER = (P_PRED * E_EV) / CHUNKS;   // 24
    if (tid < QPER) {
        int q = chunk * QPER + tid;
        int h = q >> 7, eq = q & 127;
        if (eq >= 1 && sm[h][eq] > 0.0f) {
            float tq = st[h][eq];
            float feat;
            if (h == 0) {
                float k1 = kernel_sum_one(ct[1], tq);
                float k2 = kernel_sum_one(ct[2], tq);
                feat = __fadd_rn(k1, k2);
            } else {
                feat = kernel_sum_one(ct[0], tq);
            }
            float bh = (h == 0) ? b0 : (h == 1) ? b1 : b2;
            float wh = (h == 0) ? w0 : (h == 1) ? w1 : w2;
            acc_log += (double)logf(lam_of(wh, feat, bh));
        }
    }

    // ---- deterministic block reduce ----
    red[tid] = acc_log - (double)RES_D * acc_int;
    __syncthreads();
#pragma unroll
    for (int off = TPB / 2; off > 0; off >>= 1) {
        if (tid < off) red[tid] += red[tid + off];
        __syncthreads();
    }
    if (tid == 0) {
        g_partials[blockIdx.x] = red[0];
        __threadfence();
        int old = atomicAdd(&g_counter, 1);
        islast = (old == NB - 1) ? 1 : 0;
    }
    __syncthreads();

    // ---- last block: fixed-order final reduce (deterministic) ----
    if (islast) {
        __threadfence();
        const int PERT = (NB + TPB - 1) / TPB;
        double a = 0.0;
        int b0i = tid * PERT;
#pragma unroll 4
        for (int i = 0; i < PERT; ++i) {
            int idx = b0i + i;
            if (idx < NB) a += g_partials[idx];
        }
        red[tid] = a;
        __syncthreads();
#pragma unroll
        for (int off = TPB / 2; off > 0; off >>= 1) {
            if (tid < off) red[tid] += red[tid + off];
            __syncthreads();
        }
        if (tid == 0) {
            out[0] = (float)red[0];
            g_counter = 0;   // reset for next replay
        }
    }
}

extern "C" void kernel_launch(void* const* d_in, const int* in_sizes, int n_in,
                              void* d_out, int out_size) {
    const float* event_times = (const float*)d_in[0];
    const float* event_mask  = (const float*)d_in[1];
    const float* base        = (const float*)d_in[2];
    const float* weight      = (const float*)d_in[3];
    const void*  tmax        = d_in[4];

    int S = in_sizes[0] / (P_PRED * E_EV);
    int nblocks = S * CHUNKS;

    hawkes_fused<<<nblocks, TPB>>>(event_times, event_mask, base, weight, tmax,
                                   (float*)d_out);
}

// round 6
// speedup vs baseline: 1.8276x; 1.5496x over previous
#include <cuda_runtime.h>
#include <math.h>

// Problem constants (fixed by the dataset)
#define P_PRED 3
#define E_EV   128
#define CHUNKS 4
#define TPB    128

#define TIME_TOL 0.1f
#define DECAY    0.8f
#define RES_D    0.03

// Scratch (no device allocation allowed anywhere).
__device__ double g_partials[2048];
__device__ int    g_counter = 0;

__device__ __forceinline__ float final_intensity(float raw, float base) {
    return (raw >= 0.0f) ? fmaxf(raw, base) : __expf(raw);
}

__device__ __forceinline__ float lam_of(float w, float feat, float b) {
    float raw = __fadd_rn(b, __fmul_rn(w, feat));   // mirror ref: mul then add
    return final_intensity(raw, b);
}

// Branchless count of events with (t - st[e]) > 0.1f on sorted st[0..128).
// 7 power-of-two probes decide bits of K in [0,127]; the 8th probe fixes K=128.
// Predicate is the reference's f32 comparison -> inclusion set is bit-exact.
__device__ __forceinline__ int cut_count(const float* __restrict__ st, float t) {
    int c = 0;
#pragma unroll
    for (int step = 64; step >= 1; step >>= 1)
        if ((t - st[c + step - 1]) > TIME_TOL) c += step;
    // c in [0,127]: one more probe handles the K == 128 case exactly.
    if ((t - st[c]) > TIME_TOL) ++c;
    return c;
}

__global__ __launch_bounds__(TPB)
void hawkes_fused(const float* __restrict__ event_times,
                  const float* __restrict__ event_mask,
                  const float* __restrict__ base,
                  const float* __restrict__ weight,
                  const void*  __restrict__ tmax_ptr,
                  float* __restrict__ out) {
    const int s     = blockIdx.x / CHUNKS;
    const int chunk = blockIdx.x % CHUNKS;
    const int tid   = threadIdx.x;
    const int NB    = gridDim.x;

    __shared__ float st[P_PRED][E_EV];        // sorted event times
    __shared__ float sm[P_PRED][E_EV];        // masks
    __shared__ float pref[P_PRED][E_EV + 1];  // f32 prefix of m*exp(0.8*te) (f64 scan)
    __shared__ float sb[P_PRED], sw[P_PRED];
    __shared__ double red[TPB];
    __shared__ int islast;

    const float* et = event_times + (size_t)s * P_PRED * E_EV;
    const float* em = event_mask  + (size_t)s * P_PRED * E_EV;
    for (int i = tid; i < P_PRED * E_EV; i += TPB) {
        int p = i >> 7, e = i & 127;
        st[p][e] = et[i];
        sm[p][e] = em[i];
    }
    if (tid < P_PRED) { sb[tid] = base[tid]; sw[tid] = weight[tid]; }
    __syncthreads();

    // f64 warp-scan of m_e * __expf(0.8*te) per predicate (warp w -> pred w).
    const int wid = tid >> 5, lane = tid & 31;
    if (wid < P_PRED) {
        double carry = 0.0;
#pragma unroll
        for (int seg = 0; seg < E_EV / 32; ++seg) {
            int e = seg * 32 + lane;
            double v = (double)__fmul_rn(sm[wid][e], __expf(__fmul_rn(DECAY, st[wid][e])));
#pragma unroll
            for (int o = 1; o < 32; o <<= 1) {
                double n = __shfl_up_sync(0xffffffffu, v, o);
                if (lane >= o) v += n;
            }
            v += carry;
            pref[wid][e + 1] = (float)v;
            carry = __shfl_sync(0xffffffffu, v, 31);
        }
        if (lane == 0) pref[wid][0] = 0.0f;
    }
    __syncthreads();

    // Grid count G = ceil(T_max / 0.03); T_max may arrive as int or f32.
    int tmax_i = *(const int*)tmax_ptr;
    if (!(tmax_i > 0 && tmax_i < 1000000)) tmax_i = (int)(*(const float*)tmax_ptr);
    const int G = (int)ceil((double)tmax_i / RES_D);

    const float b0 = sb[0], b1 = sb[1], b2 = sb[2];
    const float w0 = sw[0], w1 = sw[1], w2 = sw[2];

    double acc = 0.0;   // acc_log - RES * acc_int, accumulated as they come

    // ---- integral term over this chunk's grid points ----
    const int per = (G + CHUNKS - 1) / CHUNKS;
    const int gs = chunk * per;
    const int ge = min(gs + per, G);
    double acc_int = 0.0;
    for (int g = gs + tid; g < ge; g += TPB) {
        float t = (float)((double)g * RES_D);   // matches np.arange(f64) -> f32
        float edk = __expf(__fmul_rn(-DECAY, t));

        // Three interleaved branchless searches (independent LDS chains).
        int c0 = 0, c1 = 0, c2 = 0;
#pragma unroll
        for (int step = 64; step >= 1; step >>= 1) {
            if ((t - st[0][c0 + step - 1]) > TIME_TOL) c0 += step;
            if ((t - st[1][c1 + step - 1]) > TIME_TOL) c1 += step;
            if ((t - st[2][c2 + step - 1]) > TIME_TOL) c2 += step;
        }
        if ((t - st[0][c0]) > TIME_TOL) ++c0;
        if ((t - st[1][c1]) > TIME_TOL) ++c1;
        if ((t - st[2][c2]) > TIME_TOL) ++c2;

        float k0 = __fmul_rn(edk, pref[0][c0]);
        float k1 = __fmul_rn(edk, pref[1][c1]);
        float k2 = __fmul_rn(edk, pref[2][c2]);

        // BODY = [[0,1,1],[1,0,0],[1,0,0]]
        float l0 = lam_of(w0, __fadd_rn(k1, k2), b0);
        float l1 = lam_of(w1, k0, b1);
        float l2 = lam_of(w2, k0, b2);
        acc_int += (double)(l0 + l1 + l2);
    }
    acc -= (double)RES_D * acc_int;

    // ---- log-sum term: each head's own event times, eq >= 1, mask > 0 ----
    const int QPER = (P_PRED * E_EV) / CHUNKS;   // 96
    if (tid < QPER) {
        int q = chunk * QPER + tid;
        int h = q >> 7, eq = q & 127;
        if (eq >= 1 && sm[h][eq] > 0.0f) {
            float tq = st[h][eq];
            float edk = __expf(__fmul_rn(-DECAY, tq));
            float feat;
            if (h == 0) {
                float k1 = __fmul_rn(edk, pref[1][cut_count(st[1], tq)]);
                float k2 = __fmul_rn(edk, pref[2][cut_count(st[2], tq)]);
                feat = __fadd_rn(k1, k2);
            } else {
                feat = __fmul_rn(edk, pref[0][cut_count(st[0], tq)]);
            }
            float bh = (h == 0) ? b0 : (h == 1) ? b1 : b2;
            float wh = (h == 0) ? w0 : (h == 1) ? w1 : w2;
            acc += (double)logf(lam_of(wh, feat, bh));
        }
    }

    // ---- deterministic block reduce ----
    red[tid] = acc;
    __syncthreads();
#pragma unroll
    for (int off = TPB / 2; off > 0; off >>= 1) {
        if (tid < off) red[tid] += red[tid + off];
        __syncthreads();
    }
    if (tid == 0) {
        g_partials[blockIdx.x] = red[0];
        __threadfence();
        int old = atomicAdd(&g_counter, 1);
        islast = (old == NB - 1) ? 1 : 0;
    }
    __syncthreads();

    // ---- last block: fixed-order final reduce (deterministic) ----
    if (islast) {
        __threadfence();
        const int PERT = (NB + TPB - 1) / TPB;
        double a = 0.0;
        int b0i = tid * PERT;
        for (int i = 0; i < PERT; ++i) {
            int idx = b0i + i;
            if (idx < NB) a += g_partials[idx];
        }
        red[tid] = a;
        __syncthreads();
#pragma unroll
        for (int off = TPB / 2; off > 0; off >>= 1) {
            if (tid < off) red[tid] += red[tid + off];
            __syncthreads();
        }
        if (tid == 0) {
            out[0] = (float)red[0];
            g_counter = 0;   // reset for next graph replay
        }
    }
}

extern "C" void kernel_launch(void* const* d_in, const int* in_sizes, int n_in,
                              void* d_out, int out_size) {
    const float* event_times = (const float*)d_in[0];
    const float* event_mask  = (const float*)d_in[1];
    const float* base        = (const float*)d_in[2];
    const float* weight      = (const float*)d_in[3];
    const void*  tmax        = d_in[4];

    int S = in_sizes[0] / (P_PRED * E_EV);
    int nblocks = S * CHUNKS;

    hawkes_fused<<<nblocks, TPB>>>(event_times, event_mask, base, weight, tmax,
                                   (float*)d_out);
}